// round 5
// baseline (speedup 1.0000x reference)
#include <cuda_runtime.h>
#include <cuda_bf16.h>
#include <cstdint>

// Problem constants (fixed by the dataset)
#define NN 50000
#define EE 800000
#define DIN 128
#define HC 128      // H*C
#define CC 64       // per-head channels
#define HH 2
#define ED 32

typedef unsigned long long ULL;

// ---------------------------------------------------------------------------
// Scratch (allocation-free rule: one big __device__ array, sliced by offsets)
// float region:
//   q   : N*128      k : N*128     v : N*128
//   p   : N*64   (p[n][h*32+d] = sum_c q[n][h*64+c] * We[d][h*64+c])
//   num : N*128  (unnormalized softmax-weighted sum of v[src])
//   r   : N*64   (r[n][h*32+d] = sum_{edges->n} w_h * ea_d)
//   den : N*2
// int region (aliased):
//   cnt : N        offs : N+1     curs : N     perm : E     srcs : E
// ---------------------------------------------------------------------------
#define OFF_Q    ((size_t)0)
#define OFF_K    ((size_t)6400000)
#define OFF_V    ((size_t)12800000)
#define OFF_P    ((size_t)19200000)
#define OFF_NUM  ((size_t)22400000)
#define OFF_R    ((size_t)28800000)
#define OFF_DEN  ((size_t)32000000)
#define OFF_CNT  ((size_t)32100000)
#define OFF_OFFS ((size_t)32160000)
#define OFF_CURS ((size_t)32220000)
#define OFF_PERM ((size_t)32280000)
#define OFF_SRCS ((size_t)33080000)
#define BUF_TOTAL ((size_t)33880000)

__device__ float g_buf[BUF_TOTAL];

// ---------------------------------------------------------------------------
// Packed fp32x2 helpers (Blackwell FFMA2 path — only reachable via PTX)
// ---------------------------------------------------------------------------
__device__ __forceinline__ void ffma2(ULL &d, ULL a, ULL b) {
    asm volatile("fma.rn.f32x2 %0, %1, %2, %3;" : "=l"(d) : "l"(a), "l"(b), "l"(d));
}
__device__ __forceinline__ ULL packdup(float x) {
    ULL r; asm("mov.b64 %0, {%1, %2};" : "=l"(r) : "f"(x), "f"(x)); return r;
}
__device__ __forceinline__ float2 unpack2(ULL v) {
    float2 r; asm("mov.b64 {%0, %1}, %2;" : "=f"(r.x), "=f"(r.y) : "l"(v)); return r;
}

// ---------------------------------------------------------------------------
// Kernel 1: fused node GEMMs.  out[gr][c] = sum_k x[gr][k]*W[k][c] + bias[c]
// 128x128 tile per block, 256 threads, 8x8 per thread via FFMA2 pairs.
// ---------------------------------------------------------------------------
#define ASTRIDE 130

__global__ __launch_bounds__(256, 2)
void gemm_qkvs(const float* __restrict__ x, int Nn,
               const float* __restrict__ Wq, const float* __restrict__ bq, float* __restrict__ oq,
               const float* __restrict__ Wk, const float* __restrict__ bk, float* __restrict__ ok,
               const float* __restrict__ Wv, const float* __restrict__ bv, float* __restrict__ ov,
               const float* __restrict__ Ws, const float* __restrict__ bs, float* __restrict__ os)
{
    __shared__ __align__(16) float As[32 * ASTRIDE];
    __shared__ __align__(16) float Bs[32 * 128];

    const float* W; const float* bias; float* out;
    int m = blockIdx.y;
    if (m == 0)      { W = Wq; bias = bq; out = oq; }
    else if (m == 1) { W = Wk; bias = bk; out = ok; }
    else if (m == 2) { W = Wv; bias = bv; out = ov; }
    else             { W = Ws; bias = bs; out = os; }

    int rowBase = blockIdx.x * 128;
    int tid = threadIdx.x;
    int tx = tid & 15;
    int ty = tid >> 4;

    ULL acc[4][8];
    #pragma unroll
    for (int i = 0; i < 4; i++)
        #pragma unroll
        for (int j = 0; j < 8; j++) acc[i][j] = 0ull;

    #pragma unroll
    for (int kt = 0; kt < 4; kt++) {
        int k0 = kt * 32;
        #pragma unroll
        for (int it = 0; it < 4; it++) {
            int fi  = tid + it * 256;
            int row = fi >> 3;
            int c4  = fi & 7;
            int gr  = rowBase + row;
            float4 v = make_float4(0.f, 0.f, 0.f, 0.f);
            if (gr < Nn) v = *(const float4*)(x + (size_t)gr * DIN + k0 + c4 * 4);
            As[(c4 * 4 + 0) * ASTRIDE + row] = v.x;
            As[(c4 * 4 + 1) * ASTRIDE + row] = v.y;
            As[(c4 * 4 + 2) * ASTRIDE + row] = v.z;
            As[(c4 * 4 + 3) * ASTRIDE + row] = v.w;
        }
        #pragma unroll
        for (int it = 0; it < 4; it++) {
            int fi = tid + it * 256;
            int kk = fi >> 5;
            int c4 = fi & 31;
            *(float4*)(&Bs[kk * 128 + c4 * 4]) =
                *(const float4*)(W + (size_t)(k0 + kk) * HC + c4 * 4);
        }
        __syncthreads();

        #pragma unroll
        for (int k = 0; k < 32; k++) {
            const ULL* ap = (const ULL*)(&As[k * ASTRIDE + ty * 8]);
            ULL a0 = ap[0], a1 = ap[1], a2 = ap[2], a3 = ap[3];
            float4 b03 = *(const float4*)(&Bs[k * 128 + tx * 8]);
            float4 b47 = *(const float4*)(&Bs[k * 128 + tx * 8 + 4]);
            ULL bd[8];
            bd[0] = packdup(b03.x); bd[1] = packdup(b03.y);
            bd[2] = packdup(b03.z); bd[3] = packdup(b03.w);
            bd[4] = packdup(b47.x); bd[5] = packdup(b47.y);
            bd[6] = packdup(b47.z); bd[7] = packdup(b47.w);
            #pragma unroll
            for (int j = 0; j < 8; j++) {
                ffma2(acc[0][j], a0, bd[j]);
                ffma2(acc[1][j], a1, bd[j]);
                ffma2(acc[2][j], a2, bd[j]);
                ffma2(acc[3][j], a3, bd[j]);
            }
        }
        __syncthreads();
    }

    #pragma unroll
    for (int j = 0; j < 8; j++) {
        int col = tx * 8 + j;
        float bv = __ldg(bias + col);
        #pragma unroll
        for (int i2 = 0; i2 < 4; i2++) {
            float2 v = unpack2(acc[i2][j]);
            int gr = rowBase + ty * 8 + i2 * 2;
            if (gr < Nn)     out[(size_t)gr * HC + col]       = v.x + bv;
            if (gr + 1 < Nn) out[(size_t)(gr + 1) * HC + col] = v.y + bv;
        }
    }
}

// ---------------------------------------------------------------------------
// Kernel 2: p[n][h*32+d] = sum_{c<64} q[n][h*64+c] * We[d][h*64+c]
// ---------------------------------------------------------------------------
__global__ __launch_bounds__(256)
void p_kernel(const float* __restrict__ gq, const float* __restrict__ We,
              float* __restrict__ gp, int Nn)
{
    __shared__ float Ws[32 * 129];
    for (int i = threadIdx.x; i < ED * HC; i += blockDim.x)
        Ws[(i >> 7) * 129 + (i & 127)] = __ldg(&We[i]);
    __syncthreads();

    int warpId = (blockIdx.x * blockDim.x + threadIdx.x) >> 5;
    int lane   = threadIdx.x & 31;
    int nw     = (gridDim.x * blockDim.x) >> 5;

    for (int n = warpId; n < Nn; n += nw) {
        const float* qb = gq + (size_t)n * HC;
        const float* wrow = &Ws[lane * 129];
        float acc0 = 0.f, acc1 = 0.f;
        #pragma unroll
        for (int c4 = 0; c4 < 16; c4++) {
            float4 qa = *(const float4*)(qb + c4 * 4);
            float4 qc = *(const float4*)(qb + 64 + c4 * 4);
            acc0 += qa.x * wrow[c4 * 4]     + qa.y * wrow[c4 * 4 + 1]
                  + qa.z * wrow[c4 * 4 + 2] + qa.w * wrow[c4 * 4 + 3];
            acc1 += qc.x * wrow[64 + c4 * 4]     + qc.y * wrow[64 + c4 * 4 + 1]
                  + qc.z * wrow[64 + c4 * 4 + 2] + qc.w * wrow[64 + c4 * 4 + 3];
        }
        gp[(size_t)n * 64 + lane]      = acc0;
        gp[(size_t)n * 64 + 32 + lane] = acc1;
    }
}

// ---------------------------------------------------------------------------
// CSR build: histogram -> single-block scan -> scatter
// ---------------------------------------------------------------------------
__global__ void hist_kernel(const int* __restrict__ ei, int* __restrict__ cnt, int E)
{
    int e = blockIdx.x * blockDim.x + threadIdx.x;
    if (e < E) atomicAdd(&cnt[__ldg(&ei[E + e])], 1);
}

__global__ __launch_bounds__(1024)
void scan_kernel(const int* __restrict__ cnt, int* __restrict__ offs,
                 int* __restrict__ curs, int Nn)
{
    __shared__ int wsum[32];
    int tid = threadIdx.x, lane = tid & 31, wid = tid >> 5;
    int running = 0;
    for (int base = 0; base < Nn; base += 1024) {
        int i = base + tid;
        int v = (i < Nn) ? cnt[i] : 0;
        int x = v;
        #pragma unroll
        for (int o = 1; o < 32; o <<= 1) {
            int t = __shfl_up_sync(0xffffffffu, x, o);
            if (lane >= o) x += t;
        }
        if (lane == 31) wsum[wid] = x;
        __syncthreads();
        if (wid == 0) {
            int s = wsum[lane];
            #pragma unroll
            for (int o = 1; o < 32; o <<= 1) {
                int t = __shfl_up_sync(0xffffffffu, s, o);
                if (lane >= o) s += t;
            }
            wsum[lane] = s;
        }
        __syncthreads();
        int wbase = (wid == 0) ? 0 : wsum[wid - 1];
        int excl = running + wbase + x - v;
        if (i < Nn) { offs[i] = excl; curs[i] = excl; }
        running += wsum[31];
        __syncthreads();
    }
    if (tid == 0) offs[Nn] = running;
}

__global__ void scatter_kernel(const int* __restrict__ ei, int* __restrict__ curs,
                               int* __restrict__ perm, int* __restrict__ srcs, int E)
{
    int e = blockIdx.x * blockDim.x + threadIdx.x;
    if (e < E) {
        int d = __ldg(&ei[E + e]);
        int pos = atomicAdd(&curs[d], 1);
        perm[pos] = e;
        srcs[pos] = __ldg(&ei[e]);
    }
}

// ---------------------------------------------------------------------------
// Kernel 3: dst-stationary edge aggregation. One warp per dst node.
// Lane covers channels {l, l+32} (head0) and {l+64, l+96} (head1).
// No atomics; each node's num/r/den written exactly once.
// ---------------------------------------------------------------------------
__global__ __launch_bounds__(256)
void edge_agg(const int* __restrict__ offs, const int* __restrict__ perm,
              const int* __restrict__ srcs, const float* __restrict__ ea,
              const float* __restrict__ gq, const float* __restrict__ gk,
              const float* __restrict__ gv, const float* __restrict__ gp,
              float* __restrict__ gnum, float* __restrict__ gr,
              float* __restrict__ gden, int Nn)
{
    int lane = threadIdx.x & 31;
    int n = blockIdx.x * 8 + (threadIdx.x >> 5);
    if (n >= Nn) return;

    int beg = __ldg(&offs[n]);
    int end = __ldg(&offs[n + 1]);

    const float* qb = gq + (size_t)n * HC;
    float q0 = __ldg(qb + lane),      q1 = __ldg(qb + 32 + lane);
    float q2 = __ldg(qb + 64 + lane), q3 = __ldg(qb + 96 + lane);
    float p0 = __ldg(gp + (size_t)n * 64 + lane);
    float p1 = __ldg(gp + (size_t)n * 64 + 32 + lane);

    float a0 = 0.f, a1 = 0.f, a2 = 0.f, a3 = 0.f;
    float r0 = 0.f, r1 = 0.f, d0 = 0.f, d1 = 0.f;

    for (int i = beg; i < end; i++) {
        int e   = __ldg(&perm[i]);
        int src = __ldg(&srcs[i]);
        const float* kb = gk + (size_t)src * HC;
        const float* vb = gv + (size_t)src * HC;
        float eav = __ldg(&ea[(size_t)e * ED + lane]);

        float s0 = q0 * __ldg(kb + lane)      + q1 * __ldg(kb + 32 + lane) + p0 * eav;
        float s1 = q2 * __ldg(kb + 64 + lane) + q3 * __ldg(kb + 96 + lane) + p1 * eav;
        #pragma unroll
        for (int o = 16; o > 0; o >>= 1) {
            s0 += __shfl_xor_sync(0xffffffffu, s0, o);
            s1 += __shfl_xor_sync(0xffffffffu, s1, o);
        }
        float w0 = __expf(s0 * 0.125f);   // 1/sqrt(64)
        float w1 = __expf(s1 * 0.125f);

        a0 += w0 * __ldg(vb + lane);
        a1 += w0 * __ldg(vb + 32 + lane);
        a2 += w1 * __ldg(vb + 64 + lane);
        a3 += w1 * __ldg(vb + 96 + lane);
        r0 += w0 * eav;
        r1 += w1 * eav;
        d0 += w0;
        d1 += w1;
    }

    float* nb = gnum + (size_t)n * HC;
    nb[lane] = a0; nb[32 + lane] = a1; nb[64 + lane] = a2; nb[96 + lane] = a3;
    gr[(size_t)n * 64 + lane] = r0;
    gr[(size_t)n * 64 + 32 + lane] = r1;
    if (lane == 0) { gden[2 * n] = d0; gden[2 * n + 1] = d1; }
}

// ---------------------------------------------------------------------------
// Kernel 4: finalize as FFMA2 GEMM.
//   rW = r[N,64] @ Bblk[64,128]  (Bblk = block-diag of We halves)
//   out[n][c] += (num[n][c] + rW[n][c]) / (den[n][h] + 1e-16)
// ---------------------------------------------------------------------------
__global__ __launch_bounds__(256, 2)
void finalize_gemm(const float* __restrict__ r, const float* __restrict__ num,
                   const float* __restrict__ den, const float* __restrict__ We,
                   float* __restrict__ out, int Nn)
{
    __shared__ __align__(16) float As[32 * ASTRIDE];
    __shared__ __align__(16) float Bs[32 * 128];

    int rowBase = blockIdx.x * 128;
    int tid = threadIdx.x;
    int tx = tid & 15;
    int ty = tid >> 4;

    ULL acc[4][8];
    #pragma unroll
    for (int i = 0; i < 4; i++)
        #pragma unroll
        for (int j = 0; j < 8; j++) acc[i][j] = 0ull;

    #pragma unroll
    for (int kt = 0; kt < 2; kt++) {
        int k0 = kt * 32;
        // A tile: 128 rows x 32 k from r[rowBase..][k0..k0+31]
        #pragma unroll
        for (int it = 0; it < 4; it++) {
            int fi  = tid + it * 256;
            int row = fi >> 3;
            int c4  = fi & 7;
            int gr  = rowBase + row;
            float4 v = make_float4(0.f, 0.f, 0.f, 0.f);
            if (gr < Nn) v = *(const float4*)(r + (size_t)gr * 64 + k0 + c4 * 4);
            As[(c4 * 4 + 0) * ASTRIDE + row] = v.x;
            As[(c4 * 4 + 1) * ASTRIDE + row] = v.y;
            As[(c4 * 4 + 2) * ASTRIDE + row] = v.z;
            As[(c4 * 4 + 3) * ASTRIDE + row] = v.w;
        }
        // B tile: Bblk rows d = k0..k0+31, cols 0..127 (predicated zeros)
        #pragma unroll
        for (int it = 0; it < 4; it++) {
            int fi = tid + it * 256;
            int kk = fi >> 5;
            int c  = (fi & 31) * 4;
            int d  = k0 + kk;
            float4 w = make_float4(0.f, 0.f, 0.f, 0.f);
            if (d < 32) {
                if (c < 64) w = *(const float4*)(We + (size_t)d * HC + c);
            } else {
                if (c >= 64) w = *(const float4*)(We + (size_t)(d - 32) * HC + c);
            }
            *(float4*)(&Bs[kk * 128 + c]) = w;
        }
        __syncthreads();

        #pragma unroll
        for (int k = 0; k < 32; k++) {
            const ULL* ap = (const ULL*)(&As[k * ASTRIDE + ty * 8]);
            ULL a0 = ap[0], a1 = ap[1], a2 = ap[2], a3 = ap[3];
            float4 b03 = *(const float4*)(&Bs[k * 128 + tx * 8]);
            float4 b47 = *(const float4*)(&Bs[k * 128 + tx * 8 + 4]);
            ULL bd[8];
            bd[0] = packdup(b03.x); bd[1] = packdup(b03.y);
            bd[2] = packdup(b03.z); bd[3] = packdup(b03.w);
            bd[4] = packdup(b47.x); bd[5] = packdup(b47.y);
            bd[6] = packdup(b47.z); bd[7] = packdup(b47.w);
            #pragma unroll
            for (int j = 0; j < 8; j++) {
                ffma2(acc[0][j], a0, bd[j]);
                ffma2(acc[1][j], a1, bd[j]);
                ffma2(acc[2][j], a2, bd[j]);
                ffma2(acc[3][j], a3, bd[j]);
            }
        }
        __syncthreads();
    }

    #pragma unroll
    for (int j = 0; j < 8; j++) {
        int col = tx * 8 + j;
        int h   = col >> 6;
        #pragma unroll
        for (int i2 = 0; i2 < 4; i2++) {
            float2 v = unpack2(acc[i2][j]);
            int gr = rowBase + ty * 8 + i2 * 2;
            if (gr < Nn) {
                float inv = 1.0f / (__ldg(den + 2 * gr + h) + 1e-16f);
                out[(size_t)gr * HC + col] += (num[(size_t)gr * HC + col] + v.x) * inv;
            }
            if (gr + 1 < Nn) {
                float inv = 1.0f / (__ldg(den + 2 * (gr + 1) + h) + 1e-16f);
                out[(size_t)(gr + 1) * HC + col] += (num[(size_t)(gr + 1) * HC + col] + v.y) * inv;
            }
        }
    }
}

// ---------------------------------------------------------------------------
// Launch
// inputs: 0 x, 1 edge_index, 2 edge_attr, 3 Wq, 4 bq, 5 Wk, 6 bk, 7 Wv, 8 bv,
//         9 We, 10 Wskip, 11 bskip ;  out: [N, 128] float32
// ---------------------------------------------------------------------------
extern "C" void kernel_launch(void* const* d_in, const int* in_sizes, int n_in,
                              void* d_out, int out_size)
{
    const float* x     = (const float*)d_in[0];
    const int*   ei    = (const int*)d_in[1];
    const float* ea    = (const float*)d_in[2];
    const float* Wq    = (const float*)d_in[3];
    const float* bq    = (const float*)d_in[4];
    const float* Wk    = (const float*)d_in[5];
    const float* bk    = (const float*)d_in[6];
    const float* Wv    = (const float*)d_in[7];
    const float* bv    = (const float*)d_in[8];
    const float* We    = (const float*)d_in[9];
    const float* Wsk   = (const float*)d_in[10];
    const float* bsk   = (const float*)d_in[11];
    float*       out   = (float*)d_out;

    int Nn = in_sizes[0] / DIN;
    int E  = in_sizes[1] / 2;

    float* base = nullptr;
    cudaGetSymbolAddress((void**)&base, g_buf);
    float* gq   = base + OFF_Q;
    float* gk   = base + OFF_K;
    float* gv   = base + OFF_V;
    float* gp   = base + OFF_P;
    float* gnum = base + OFF_NUM;
    float* gr   = base + OFF_R;
    float* gden = base + OFF_DEN;
    int*   cnt  = (int*)(base + OFF_CNT);
    int*   offs = (int*)(base + OFF_OFFS);
    int*   curs = (int*)(base + OFF_CURS);
    int*   perm = (int*)(base + OFF_PERM);
    int*   srcs = (int*)(base + OFF_SRCS);

    // zero only the degree histogram
    cudaMemsetAsync(cnt, 0, (size_t)Nn * sizeof(int), 0);

    // node GEMMs (skip goes straight into d_out)
    dim3 ggrid((Nn + 127) / 128, 4);
    gemm_qkvs<<<ggrid, 256>>>(x, Nn,
                              Wq, bq, gq,
                              Wk, bk, gk,
                              Wv, bv, gv,
                              Wsk, bsk, out);

    // p = q contracted with We (per head)
    p_kernel<<<1480, 256>>>(gq, We, gp, Nn);

    // CSR build by dst
    int eb = (E + 255) / 256;
    hist_kernel<<<eb, 256>>>(ei, cnt, E);
    scan_kernel<<<1, 1024>>>(cnt, offs, curs, Nn);
    scatter_kernel<<<eb, 256>>>(ei, curs, perm, srcs, E);

    // dst-stationary aggregation (no atomics)
    edge_agg<<<(Nn + 7) / 8, 256>>>(offs, perm, srcs, ea,
                                    gq, gk, gv, gp, gnum, gr, gden, Nn);

    // finalize: rW GEMM + normalize + skip
    finalize_gemm<<<(Nn + 127) / 128, 256>>>(gr, gnum, gden, We, out, Nn);
}

// round 6
// speedup vs baseline: 1.1747x; 1.1747x over previous
#include <cuda_runtime.h>
#include <cuda_bf16.h>
#include <cstdint>

// Problem constants (fixed by the dataset)
#define NN 50000
#define EE 800000
#define DIN 128
#define HC 128      // H*C
#define CC 64       // per-head channels
#define HH 2
#define ED 32

typedef unsigned long long ULL;

// ---------------------------------------------------------------------------
// Scratch layout (floats). int regions aliased.
// ---------------------------------------------------------------------------
#define OFF_Q    ((size_t)0)
#define OFF_K    ((size_t)6400000)
#define OFF_V    ((size_t)12800000)
#define OFF_P    ((size_t)19200000)
#define OFF_NUM  ((size_t)22400000)
#define OFF_R    ((size_t)28800000)
#define OFF_DEN  ((size_t)32000000)
#define OFF_CNT  ((size_t)32100000)
#define OFF_OFFS ((size_t)32160000)
#define OFF_CURS ((size_t)32220000)
#define OFF_ES   ((size_t)32280000)   // int2 per edge (e, src): 2*E ints
#define OFF_BSUM ((size_t)33880000)
#define BUF_TOTAL ((size_t)33880128)

__device__ float g_buf[BUF_TOTAL];

// ---------------------------------------------------------------------------
// Packed fp32x2 helpers (Blackwell FFMA2 path — only reachable via PTX)
// ---------------------------------------------------------------------------
__device__ __forceinline__ void ffma2(ULL &d, ULL a, ULL b) {
    asm volatile("fma.rn.f32x2 %0, %1, %2, %3;" : "=l"(d) : "l"(a), "l"(b), "l"(d));
}
__device__ __forceinline__ ULL packdup(float x) {
    ULL r; asm("mov.b64 %0, {%1, %2};" : "=l"(r) : "f"(x), "f"(x)); return r;
}
__device__ __forceinline__ float2 unpack2(ULL v) {
    float2 r; asm("mov.b64 {%0, %1}, %2;" : "=f"(r.x), "=f"(r.y) : "l"(v)); return r;
}

// ---------------------------------------------------------------------------
// Kernel 1: fused node GEMMs (q,k,v,skip). 128x128 tile, FFMA2.
// ---------------------------------------------------------------------------
#define ASTRIDE 130

__global__ __launch_bounds__(256, 2)
void gemm_qkvs(const float* __restrict__ x, int Nn,
               const float* __restrict__ Wq, const float* __restrict__ bq, float* __restrict__ oq,
               const float* __restrict__ Wk, const float* __restrict__ bk, float* __restrict__ ok,
               const float* __restrict__ Wv, const float* __restrict__ bv, float* __restrict__ ov,
               const float* __restrict__ Ws, const float* __restrict__ bs, float* __restrict__ os)
{
    __shared__ __align__(16) float As[32 * ASTRIDE];
    __shared__ __align__(16) float Bs[32 * 128];

    const float* W; const float* bias; float* out;
    int m = blockIdx.y;
    if (m == 0)      { W = Wq; bias = bq; out = oq; }
    else if (m == 1) { W = Wk; bias = bk; out = ok; }
    else if (m == 2) { W = Wv; bias = bv; out = ov; }
    else             { W = Ws; bias = bs; out = os; }

    int rowBase = blockIdx.x * 128;
    int tid = threadIdx.x;
    int tx = tid & 15;
    int ty = tid >> 4;

    ULL acc[4][8];
    #pragma unroll
    for (int i = 0; i < 4; i++)
        #pragma unroll
        for (int j = 0; j < 8; j++) acc[i][j] = 0ull;

    #pragma unroll
    for (int kt = 0; kt < 4; kt++) {
        int k0 = kt * 32;
        #pragma unroll
        for (int it = 0; it < 4; it++) {
            int fi  = tid + it * 256;
            int row = fi >> 3;
            int c4  = fi & 7;
            int gr  = rowBase + row;
            float4 v = make_float4(0.f, 0.f, 0.f, 0.f);
            if (gr < Nn) v = *(const float4*)(x + (size_t)gr * DIN + k0 + c4 * 4);
            As[(c4 * 4 + 0) * ASTRIDE + row] = v.x;
            As[(c4 * 4 + 1) * ASTRIDE + row] = v.y;
            As[(c4 * 4 + 2) * ASTRIDE + row] = v.z;
            As[(c4 * 4 + 3) * ASTRIDE + row] = v.w;
        }
        #pragma unroll
        for (int it = 0; it < 4; it++) {
            int fi = tid + it * 256;
            int kk = fi >> 5;
            int c4 = fi & 31;
            *(float4*)(&Bs[kk * 128 + c4 * 4]) =
                *(const float4*)(W + (size_t)(k0 + kk) * HC + c4 * 4);
        }
        __syncthreads();

        #pragma unroll
        for (int k = 0; k < 32; k++) {
            const ULL* ap = (const ULL*)(&As[k * ASTRIDE + ty * 8]);
            ULL a0 = ap[0], a1 = ap[1], a2 = ap[2], a3 = ap[3];
            float4 b03 = *(const float4*)(&Bs[k * 128 + tx * 8]);
            float4 b47 = *(const float4*)(&Bs[k * 128 + tx * 8 + 4]);
            ULL bd[8];
            bd[0] = packdup(b03.x); bd[1] = packdup(b03.y);
            bd[2] = packdup(b03.z); bd[3] = packdup(b03.w);
            bd[4] = packdup(b47.x); bd[5] = packdup(b47.y);
            bd[6] = packdup(b47.z); bd[7] = packdup(b47.w);
            #pragma unroll
            for (int j = 0; j < 8; j++) {
                ffma2(acc[0][j], a0, bd[j]);
                ffma2(acc[1][j], a1, bd[j]);
                ffma2(acc[2][j], a2, bd[j]);
                ffma2(acc[3][j], a3, bd[j]);
            }
        }
        __syncthreads();
    }

    #pragma unroll
    for (int j = 0; j < 8; j++) {
        int col = tx * 8 + j;
        float bv = __ldg(bias + col);
        #pragma unroll
        for (int i2 = 0; i2 < 4; i2++) {
            float2 v = unpack2(acc[i2][j]);
            int gr = rowBase + ty * 8 + i2 * 2;
            if (gr < Nn)     out[(size_t)gr * HC + col]       = v.x + bv;
            if (gr + 1 < Nn) out[(size_t)(gr + 1) * HC + col] = v.y + bv;
        }
    }
}

// ---------------------------------------------------------------------------
// Kernel 2: p[n][h*32+d] = sum_{c<64} q[n][h*64+c] * We[d][h*64+c]
// ---------------------------------------------------------------------------
__global__ __launch_bounds__(256)
void p_kernel(const float* __restrict__ gq, const float* __restrict__ We,
              float* __restrict__ gp, int Nn)
{
    __shared__ float Ws[32 * 129];
    for (int i = threadIdx.x; i < ED * HC; i += blockDim.x)
        Ws[(i >> 7) * 129 + (i & 127)] = __ldg(&We[i]);
    __syncthreads();

    int warpId = (blockIdx.x * blockDim.x + threadIdx.x) >> 5;
    int lane   = threadIdx.x & 31;
    int nw     = (gridDim.x * blockDim.x) >> 5;

    for (int n = warpId; n < Nn; n += nw) {
        const float* qb = gq + (size_t)n * HC;
        const float* wrow = &Ws[lane * 129];
        float acc0 = 0.f, acc1 = 0.f;
        #pragma unroll
        for (int c4 = 0; c4 < 16; c4++) {
            float4 qa = *(const float4*)(qb + c4 * 4);
            float4 qc = *(const float4*)(qb + 64 + c4 * 4);
            acc0 += qa.x * wrow[c4 * 4]     + qa.y * wrow[c4 * 4 + 1]
                  + qa.z * wrow[c4 * 4 + 2] + qa.w * wrow[c4 * 4 + 3];
            acc1 += qc.x * wrow[64 + c4 * 4]     + qc.y * wrow[64 + c4 * 4 + 1]
                  + qc.z * wrow[64 + c4 * 4 + 2] + qc.w * wrow[64 + c4 * 4 + 3];
        }
        gp[(size_t)n * 64 + lane]      = acc0;
        gp[(size_t)n * 64 + 32 + lane] = acc1;
    }
}

// ---------------------------------------------------------------------------
// CSR build: histogram -> 3-phase parallel scan -> scatter (int2 stream)
// ---------------------------------------------------------------------------
__global__ void hist_kernel(const int* __restrict__ ei, int* __restrict__ cnt, int E)
{
    int e = blockIdx.x * blockDim.x + threadIdx.x;
    if (e < E) atomicAdd(&cnt[__ldg(&ei[E + e])], 1);
}

// Phase 1: per-block (1024 elems) local exclusive scan + block total
__global__ __launch_bounds__(1024)
void scan_block(const int* __restrict__ cnt, int* __restrict__ offs,
                int* __restrict__ bsum, int Nn)
{
    __shared__ int wsum[32];
    int tid = threadIdx.x, lane = tid & 31, wid = tid >> 5;
    int i = blockIdx.x * 1024 + tid;
    int v = (i < Nn) ? cnt[i] : 0;
    int x = v;
    #pragma unroll
    for (int o = 1; o < 32; o <<= 1) {
        int t = __shfl_up_sync(0xffffffffu, x, o);
        if (lane >= o) x += t;
    }
    if (lane == 31) wsum[wid] = x;
    __syncthreads();
    if (wid == 0) {
        int s = wsum[lane];
        #pragma unroll
        for (int o = 1; o < 32; o <<= 1) {
            int t = __shfl_up_sync(0xffffffffu, s, o);
            if (lane >= o) s += t;
        }
        wsum[lane] = s;
    }
    __syncthreads();
    int wbase = (wid == 0) ? 0 : wsum[wid - 1];
    if (i < Nn) offs[i] = wbase + x - v;
    if (tid == 1023) bsum[blockIdx.x] = wsum[31];
}

// Phase 2: serial scan of block totals (tiny)
__global__ void scan_tops(int* __restrict__ bsum, int* __restrict__ offs, int Nn, int nb)
{
    if (threadIdx.x == 0) {
        int run = 0;
        for (int b = 0; b < nb; b++) { int t = bsum[b]; bsum[b] = run; run += t; }
        offs[Nn] = run;
    }
}

// Phase 3: add block prefixes
__global__ __launch_bounds__(1024)
void scan_add(int* __restrict__ offs, int* __restrict__ curs,
              const int* __restrict__ bsum, int Nn)
{
    int i = blockIdx.x * 1024 + threadIdx.x;
    if (i < Nn) {
        int o = offs[i] + __ldg(&bsum[blockIdx.x]);
        offs[i] = o;
        curs[i] = o;
    }
}

__global__ void scatter_kernel(const int* __restrict__ ei, int* __restrict__ curs,
                               int2* __restrict__ es, int E)
{
    int e = blockIdx.x * blockDim.x + threadIdx.x;
    if (e < E) {
        int d = __ldg(&ei[E + e]);
        int pos = atomicAdd(&curs[d], 1);
        es[pos] = make_int2(e, __ldg(&ei[e]));
    }
}

// ---------------------------------------------------------------------------
// Kernel 3: dst-stationary edge aggregation. One warp per dst node.
// Lane l owns contiguous channels [4l, 4l+4): lanes 0-15 = head 0, 16-31 = head 1.
// Half-warp butterfly (xor 8,4,2,1) reduces both heads simultaneously; each
// lane only needs its own half's weight. No atomics.
// ---------------------------------------------------------------------------
__global__ __launch_bounds__(256)
void edge_agg(const int* __restrict__ offs, const int2* __restrict__ es,
              const float* __restrict__ ea,
              const float* __restrict__ gq, const float* __restrict__ gk,
              const float* __restrict__ gv, const float* __restrict__ gp,
              float* __restrict__ gnum, float* __restrict__ gr,
              float* __restrict__ gden, int Nn)
{
    int lane = threadIdx.x & 31;
    int n = blockIdx.x * 8 + (threadIdx.x >> 5);
    if (n >= Nn) return;

    int h = lane >> 4;          // head
    int j = lane & 15;          // lane within head

    int beg = __ldg(&offs[n]);
    int end = __ldg(&offs[n + 1]);

    float4 q4 = __ldg((const float4*)(gq + (size_t)n * HC + 4 * lane));
    float2 p2 = __ldg((const float2*)(gp + (size_t)n * 64 + h * 32 + 2 * j));

    float a0 = 0.f, a1 = 0.f, a2 = 0.f, a3 = 0.f;
    float r0 = 0.f, r1 = 0.f, dw = 0.f;

    int i = beg;
    for (; i + 2 <= end; i += 2) {
        int2 eA = __ldg(&es[i]);
        int2 eB = __ldg(&es[i + 1]);
        float4 kA = __ldg((const float4*)(gk + (size_t)eA.y * HC + 4 * lane));
        float4 kB = __ldg((const float4*)(gk + (size_t)eB.y * HC + 4 * lane));
        float4 vA = __ldg((const float4*)(gv + (size_t)eA.y * HC + 4 * lane));
        float4 vB = __ldg((const float4*)(gv + (size_t)eB.y * HC + 4 * lane));
        float2 cA = __ldg((const float2*)(ea + (size_t)eA.x * ED + 2 * j));
        float2 cB = __ldg((const float2*)(ea + (size_t)eB.x * ED + 2 * j));

        float sA = q4.x * kA.x + q4.y * kA.y + q4.z * kA.z + q4.w * kA.w
                 + cA.x * p2.x + cA.y * p2.y;
        float sB = q4.x * kB.x + q4.y * kB.y + q4.z * kB.z + q4.w * kB.w
                 + cB.x * p2.x + cB.y * p2.y;
        #pragma unroll
        for (int o = 8; o > 0; o >>= 1) {
            sA += __shfl_xor_sync(0xffffffffu, sA, o);
            sB += __shfl_xor_sync(0xffffffffu, sB, o);
        }
        float wA = __expf(sA * 0.125f);   // 1/sqrt(64)
        float wB = __expf(sB * 0.125f);

        a0 += wA * vA.x + wB * vB.x;
        a1 += wA * vA.y + wB * vB.y;
        a2 += wA * vA.z + wB * vB.z;
        a3 += wA * vA.w + wB * vB.w;
        r0 += wA * cA.x + wB * cB.x;
        r1 += wA * cA.y + wB * cB.y;
        dw += wA + wB;
    }
    if (i < end) {
        int2 eA = __ldg(&es[i]);
        float4 kA = __ldg((const float4*)(gk + (size_t)eA.y * HC + 4 * lane));
        float4 vA = __ldg((const float4*)(gv + (size_t)eA.y * HC + 4 * lane));
        float2 cA = __ldg((const float2*)(ea + (size_t)eA.x * ED + 2 * j));
        float sA = q4.x * kA.x + q4.y * kA.y + q4.z * kA.z + q4.w * kA.w
                 + cA.x * p2.x + cA.y * p2.y;
        #pragma unroll
        for (int o = 8; o > 0; o >>= 1)
            sA += __shfl_xor_sync(0xffffffffu, sA, o);
        float wA = __expf(sA * 0.125f);
        a0 += wA * vA.x; a1 += wA * vA.y; a2 += wA * vA.z; a3 += wA * vA.w;
        r0 += wA * cA.x; r1 += wA * cA.y;
        dw += wA;
    }

    *(float4*)(gnum + (size_t)n * HC + 4 * lane) = make_float4(a0, a1, a2, a3);
    *(float2*)(gr + (size_t)n * 64 + h * 32 + 2 * j) = make_float2(r0, r1);
    if (j == 0) gden[2 * n + h] = dw;
}

// ---------------------------------------------------------------------------
// Kernel 4: finalize as FFMA2 GEMM.
//   rW = r[N,64] @ Bblk[64,128]  (Bblk = block-diag of We halves)
//   out[n][c] += (num[n][c] + rW[n][c]) / (den[n][h] + 1e-16)
// ---------------------------------------------------------------------------
__global__ __launch_bounds__(256, 2)
void finalize_gemm(const float* __restrict__ r, const float* __restrict__ num,
                   const float* __restrict__ den, const float* __restrict__ We,
                   float* __restrict__ out, int Nn)
{
    __shared__ __align__(16) float As[32 * ASTRIDE];
    __shared__ __align__(16) float Bs[32 * 128];

    int rowBase = blockIdx.x * 128;
    int tid = threadIdx.x;
    int tx = tid & 15;
    int ty = tid >> 4;

    ULL acc[4][8];
    #pragma unroll
    for (int i = 0; i < 4; i++)
        #pragma unroll
        for (int j = 0; j < 8; j++) acc[i][j] = 0ull;

    #pragma unroll
    for (int kt = 0; kt < 2; kt++) {
        int k0 = kt * 32;
        #pragma unroll
        for (int it = 0; it < 4; it++) {
            int fi  = tid + it * 256;
            int row = fi >> 3;
            int c4  = fi & 7;
            int gr  = rowBase + row;
            float4 v = make_float4(0.f, 0.f, 0.f, 0.f);
            if (gr < Nn) v = *(const float4*)(r + (size_t)gr * 64 + k0 + c4 * 4);
            As[(c4 * 4 + 0) * ASTRIDE + row] = v.x;
            As[(c4 * 4 + 1) * ASTRIDE + row] = v.y;
            As[(c4 * 4 + 2) * ASTRIDE + row] = v.z;
            As[(c4 * 4 + 3) * ASTRIDE + row] = v.w;
        }
        #pragma unroll
        for (int it = 0; it < 4; it++) {
            int fi = tid + it * 256;
            int kk = fi >> 5;
            int c  = (fi & 31) * 4;
            int d  = k0 + kk;
            float4 w = make_float4(0.f, 0.f, 0.f, 0.f);
            if (d < 32) {
                if (c < 64) w = *(const float4*)(We + (size_t)d * HC + c);
            } else {
                if (c >= 64) w = *(const float4*)(We + (size_t)(d - 32) * HC + c);
            }
            *(float4*)(&Bs[kk * 128 + c]) = w;
        }
        __syncthreads();

        #pragma unroll
        for (int k = 0; k < 32; k++) {
            const ULL* ap = (const ULL*)(&As[k * ASTRIDE + ty * 8]);
            ULL a0 = ap[0], a1 = ap[1], a2 = ap[2], a3 = ap[3];
            float4 b03 = *(const float4*)(&Bs[k * 128 + tx * 8]);
            float4 b47 = *(const float4*)(&Bs[k * 128 + tx * 8 + 4]);
            ULL bd[8];
            bd[0] = packdup(b03.x); bd[1] = packdup(b03.y);
            bd[2] = packdup(b03.z); bd[3] = packdup(b03.w);
            bd[4] = packdup(b47.x); bd[5] = packdup(b47.y);
            bd[6] = packdup(b47.z); bd[7] = packdup(b47.w);
            #pragma unroll
            for (int j = 0; j < 8; j++) {
                ffma2(acc[0][j], a0, bd[j]);
                ffma2(acc[1][j], a1, bd[j]);
                ffma2(acc[2][j], a2, bd[j]);
                ffma2(acc[3][j], a3, bd[j]);
            }
        }
        __syncthreads();
    }

    #pragma unroll
    for (int j = 0; j < 8; j++) {
        int col = tx * 8 + j;
        int h   = col >> 6;
        #pragma unroll
        for (int i2 = 0; i2 < 4; i2++) {
            float2 v = unpack2(acc[i2][j]);
            int gr = rowBase + ty * 8 + i2 * 2;
            if (gr < Nn) {
                float inv = 1.0f / (__ldg(den + 2 * gr + h) + 1e-16f);
                out[(size_t)gr * HC + col] += (num[(size_t)gr * HC + col] + v.x) * inv;
            }
            if (gr + 1 < Nn) {
                float inv = 1.0f / (__ldg(den + 2 * (gr + 1) + h) + 1e-16f);
                out[(size_t)(gr + 1) * HC + col] += (num[(size_t)(gr + 1) * HC + col] + v.y) * inv;
            }
        }
    }
}

// ---------------------------------------------------------------------------
// Launch
// ---------------------------------------------------------------------------
extern "C" void kernel_launch(void* const* d_in, const int* in_sizes, int n_in,
                              void* d_out, int out_size)
{
    const float* x     = (const float*)d_in[0];
    const int*   ei    = (const int*)d_in[1];
    const float* ea    = (const float*)d_in[2];
    const float* Wq    = (const float*)d_in[3];
    const float* bq    = (const float*)d_in[4];
    const float* Wk    = (const float*)d_in[5];
    const float* bk    = (const float*)d_in[6];
    const float* Wv    = (const float*)d_in[7];
    const float* bv    = (const float*)d_in[8];
    const float* We    = (const float*)d_in[9];
    const float* Wsk   = (const float*)d_in[10];
    const float* bsk   = (const float*)d_in[11];
    float*       out   = (float*)d_out;

    int Nn = in_sizes[0] / DIN;
    int E  = in_sizes[1] / 2;

    float* base = nullptr;
    cudaGetSymbolAddress((void**)&base, g_buf);
    float* gq   = base + OFF_Q;
    float* gk   = base + OFF_K;
    float* gv   = base + OFF_V;
    float* gp   = base + OFF_P;
    float* gnum = base + OFF_NUM;
    float* gr   = base + OFF_R;
    float* gden = base + OFF_DEN;
    int*   cnt  = (int*)(base + OFF_CNT);
    int*   offs = (int*)(base + OFF_OFFS);
    int*   curs = (int*)(base + OFF_CURS);
    int2*  es   = (int2*)(base + OFF_ES);
    int*   bsum = (int*)(base + OFF_BSUM);

    // zero only the degree histogram
    cudaMemsetAsync(cnt, 0, (size_t)Nn * sizeof(int), 0);

    // node GEMMs (skip goes straight into d_out)
    dim3 ggrid((Nn + 127) / 128, 4);
    gemm_qkvs<<<ggrid, 256>>>(x, Nn,
                              Wq, bq, gq,
                              Wk, bk, gk,
                              Wv, bv, gv,
                              Wsk, bsk, out);

    // p = q contracted with We (per head)
    p_kernel<<<1480, 256>>>(gq, We, gp, Nn);

    // CSR build by dst (parallel scan)
    int eb = (E + 255) / 256;
    int nb = (Nn + 1023) / 1024;
    hist_kernel<<<eb, 256>>>(ei, cnt, E);
    scan_block<<<nb, 1024>>>(cnt, offs, bsum, Nn);
    scan_tops<<<1, 32>>>(bsum, offs, Nn, nb);
    scan_add<<<nb, 1024>>>(offs, curs, bsum, Nn);
    scatter_kernel<<<eb, 256>>>(ei, curs, es, E);

    // dst-stationary aggregation (no atomics)
    edge_agg<<<(Nn + 7) / 8, 256>>>(offs, es, ea, gq, gk, gv, gp,
                                    gnum, gr, gden, Nn);

    // finalize: rW GEMM + normalize + skip
    finalize_gemm<<<(Nn + 127) / 128, 256>>>(gr, gnum, gden, We, out, Nn);
}